// round 6
// baseline (speedup 1.0000x reference)
#include <cuda_runtime.h>

// TensorNeRF compositing: block-compacted two-phase.
// Phase A (thread-per-ray, coalesced): slab-test all 256 rays of the block;
// misses write outputs immediately; hits compact into smem.
// Phase B (warp-per-hit-ray): exact-predicate scan composite over the
// conservative chunk window, ray params served from smem.
// Out-of-bbox samples have factor (1-0+1e-10)==1.0f exactly in f32, so
// skipping them is exact.

#define S_SAMPLES 512
#define RAYS_PER_BLOCK 256

__global__ __launch_bounds__(256) void nerf_composite_kernel(
    const float* __restrict__ rays_o,
    const float* __restrict__ rays_d,
    const float* __restrict__ sigma_feat,
    const float* __restrict__ rgb,
    const float* __restrict__ aabb,
    float* __restrict__ out,
    int N)
{
    __shared__ int   s_cnt;
    __shared__ int   s_ray[RAYS_PER_BLOCK];
    __shared__ int   s_win[RAYS_PER_BLOCK];      // packed c0 | c1<<16
    __shared__ float s_par[RAYS_PER_BLOCK][6];   // ox oy oz dx dy dz

    const int tid = threadIdx.x;
    if (tid == 0) s_cnt = 0;
    __syncthreads();

    const float ax0 = aabb[0], ay0 = aabb[1], az0 = aabb[2];
    const float ax1 = aabb[3], ay1 = aabb[4], az1 = aabb[5];

    const float NEAR = 2.0f, FAR = 6.0f;
    const float DENSITY_SHIFT = -10.0f;
    const float step = 4.0f / 511.0f;
    const float dist = step * 25.0f;

    // ---- Phase A: thread-per-ray slab test (coalesced loads) ----
    const int ray = blockIdx.x * RAYS_PER_BLOCK + tid;
    {
        const float ox = rays_o[ray * 3 + 0];
        const float oy = rays_o[ray * 3 + 1];
        const float oz = rays_o[ray * 3 + 2];
        const float dx = rays_d[ray * 3 + 0];
        const float dy = rays_d[ray * 3 + 1];
        const float dz = rays_d[ray * 3 + 2];

        const float idx_ = __frcp_rn(dx);
        const float idy_ = __frcp_rn(dy);
        const float idz_ = __frcp_rn(dz);
        const float txa = (ax0 - ox) * idx_, txb = (ax1 - ox) * idx_;
        const float tya = (ay0 - oy) * idy_, tyb = (ay1 - oy) * idy_;
        const float tza = (az0 - oz) * idz_, tzb = (az1 - oz) * idz_;
        float t_ent = fmaxf(fmaxf(fminf(txa, txb), fminf(tya, tyb)), fminf(tza, tzb));
        float t_exi = fminf(fminf(fmaxf(txa, txb), fmaxf(tya, tyb)), fmaxf(tza, tzb));
        t_ent = fmaxf(t_ent, NEAR);
        t_exi = fminf(t_exi, FAR);

        bool miss = (t_ent > t_exi + 2.0f * step);
        int c0 = 0, c1 = -1;
        if (!miss) {
            int s_lo = __float2int_rd((t_ent - NEAR) * (511.0f / 4.0f)) - 2;
            int s_hi = __float2int_ru((t_exi - NEAR) * (511.0f / 4.0f)) + 2;
            s_lo = max(s_lo, 0);
            s_hi = min(s_hi, S_SAMPLES - 1);
            if (s_lo > s_hi) miss = true;
            else { c0 = s_lo >> 5; c1 = s_hi >> 5; }
        }

        if (miss) {
            out[ray * 3 + 0] = 0.0f;
            out[ray * 3 + 1] = 0.0f;
            out[ray * 3 + 2] = 0.0f;
            out[3 * N + ray] = 0.0f;
            out[4 * N + ray] = 1.0f;
        } else {
            const int h = atomicAdd(&s_cnt, 1);
            s_ray[h] = ray;
            s_win[h] = c0 | (c1 << 16);
            s_par[h][0] = ox; s_par[h][1] = oy; s_par[h][2] = oz;
            s_par[h][3] = dx; s_par[h][4] = dy; s_par[h][5] = dz;
        }
    }
    __syncthreads();

    // ---- Phase B: warp-per-hit-ray composite ----
    const int nh   = s_cnt;
    const int wid  = tid >> 5;
    const int lane = tid & 31;

    for (int h = wid; h < nh; h += 8) {
        const int   r  = s_ray[h];
        const int   w_ = s_win[h];
        const int   c0 = w_ & 0xffff;
        const int   c1 = w_ >> 16;
        const float ox = s_par[h][0], oy = s_par[h][1], oz = s_par[h][2];
        const float dx = s_par[h][3], dy = s_par[h][4], dz = s_par[h][5];

        const float* __restrict__ sf = sigma_feat + (size_t)r * S_SAMPLES;
        const float* __restrict__ rg = rgb + (size_t)r * S_SAMPLES * 3;

        float runT = 1.0f;
        float racc = 0.0f, gacc = 0.0f, bacc = 0.0f, dacc = 0.0f;

        #pragma unroll 1
        for (int c = c0; c <= c1; ++c) {
            const int s = c * 32 + lane;
            const float t = fmaf(step, (float)s, NEAR);
            const float px = fmaf(dx, t, ox);
            const float py = fmaf(dy, t, oy);
            const float pz = fmaf(dz, t, oz);
            const bool inb = (px >= ax0) & (px <= ax1) &
                             (py >= ay0) & (py <= ay1) &
                             (pz >= az0) & (pz <= az1);

            const float x = sf[s] + DENSITY_SHIFT;
            float sp = (x > 20.0f) ? x : __logf(1.0f + __expf(x));
            const float sigma = inb ? sp : 0.0f;

            const float e = __expf(-sigma * dist);
            const float alpha = 1.0f - e;
            const float f = e + 1e-10f;

            float incl = f;
            #pragma unroll
            for (int off = 1; off < 32; off <<= 1) {
                const float v = __shfl_up_sync(0xffffffffu, incl, off);
                if (lane >= off) incl *= v;
            }
            float excl = __shfl_up_sync(0xffffffffu, incl, 1);
            if (lane == 0) excl = 1.0f;

            const float w = alpha * runT * excl;

            racc += w * rg[s * 3 + 0];
            gacc += w * rg[s * 3 + 1];
            bacc += w * rg[s * 3 + 2];
            dacc += w * t;

            runT *= __shfl_sync(0xffffffffu, incl, 31);
        }

        #pragma unroll
        for (int off = 16; off; off >>= 1) {
            racc += __shfl_down_sync(0xffffffffu, racc, off);
            gacc += __shfl_down_sync(0xffffffffu, gacc, off);
            bacc += __shfl_down_sync(0xffffffffu, bacc, off);
            dacc += __shfl_down_sync(0xffffffffu, dacc, off);
        }

        if (lane == 0) {
            out[r * 3 + 0] = racc;
            out[r * 3 + 1] = gacc;
            out[r * 3 + 2] = bacc;
            out[3 * N + r] = dacc;
            out[4 * N + r] = runT;
        }
    }
}

extern "C" void kernel_launch(void* const* d_in, const int* in_sizes, int n_in,
                              void* d_out, int out_size) {
    const float* rays_o     = (const float*)d_in[0];
    const float* rays_d     = (const float*)d_in[1];
    const float* sigma_feat = (const float*)d_in[2];
    const float* rgb        = (const float*)d_in[3];
    const float* aabb       = (const float*)d_in[4];
    float* out = (float*)d_out;

    const int N = in_sizes[0] / 3;
    const int grid = (N + RAYS_PER_BLOCK - 1) / RAYS_PER_BLOCK;

    nerf_composite_kernel<<<grid, 256>>>(rays_o, rays_d, sigma_feat, rgb, aabb, out, N);
}

// round 7
// speedup vs baseline: 1.3459x; 1.3459x over previous
#include <cuda_runtime.h>

// TensorNeRF compositing: globally-compacted two-phase.
//  K0: reset global hit counter.
//  K1 (thread-per-ray): slab test; misses write outputs; hits append to a
//      global queue (ray id + conservative chunk window).
//  K2 (warp-per-hit-ray, grid-stride): exact-predicate scan composite.
// Out-of-bbox samples have cumprod factor (1-0+1e-10)==1.0f exactly in f32,
// so restricting to the conservative window is exact.

#define S_SAMPLES 512
#define MAX_RAYS 32768

__device__ int g_cnt;
__device__ int2 g_queue[MAX_RAYS];   // (ray, c0 | c1<<16)

__global__ void reset_kernel() { g_cnt = 0; }

__global__ __launch_bounds__(128) void phaseA_kernel(
    const float* __restrict__ rays_o,
    const float* __restrict__ rays_d,
    const float* __restrict__ aabb,
    float* __restrict__ out,
    int N)
{
    const int ray = blockIdx.x * blockDim.x + threadIdx.x;
    if (ray >= N) return;

    const float ax0 = aabb[0], ay0 = aabb[1], az0 = aabb[2];
    const float ax1 = aabb[3], ay1 = aabb[4], az1 = aabb[5];
    const float NEAR = 2.0f, FAR = 6.0f;
    const float step = 4.0f / 511.0f;

    const float ox = rays_o[ray * 3 + 0];
    const float oy = rays_o[ray * 3 + 1];
    const float oz = rays_o[ray * 3 + 2];
    const float dx = rays_d[ray * 3 + 0];
    const float dy = rays_d[ray * 3 + 1];
    const float dz = rays_d[ray * 3 + 2];

    const float idx_ = __frcp_rn(dx);
    const float idy_ = __frcp_rn(dy);
    const float idz_ = __frcp_rn(dz);
    const float txa = (ax0 - ox) * idx_, txb = (ax1 - ox) * idx_;
    const float tya = (ay0 - oy) * idy_, tyb = (ay1 - oy) * idy_;
    const float tza = (az0 - oz) * idz_, tzb = (az1 - oz) * idz_;
    float t_ent = fmaxf(fmaxf(fminf(txa, txb), fminf(tya, tyb)), fminf(tza, tzb));
    float t_exi = fminf(fminf(fmaxf(txa, txb), fmaxf(tya, tyb)), fmaxf(tza, tzb));
    t_ent = fmaxf(t_ent, NEAR);
    t_exi = fminf(t_exi, FAR);

    bool miss = (t_ent > t_exi + 2.0f * step);
    int c0 = 0, c1 = -1;
    if (!miss) {
        int s_lo = __float2int_rd((t_ent - NEAR) * (511.0f / 4.0f)) - 2;
        int s_hi = __float2int_ru((t_exi - NEAR) * (511.0f / 4.0f)) + 2;
        s_lo = max(s_lo, 0);
        s_hi = min(s_hi, S_SAMPLES - 1);
        if (s_lo > s_hi) miss = true;
        else { c0 = s_lo >> 5; c1 = s_hi >> 5; }
    }

    if (miss) {
        out[ray * 3 + 0] = 0.0f;
        out[ray * 3 + 1] = 0.0f;
        out[ray * 3 + 2] = 0.0f;
        out[3 * N + ray] = 0.0f;
        out[4 * N + ray] = 1.0f;
    } else {
        const int h = atomicAdd(&g_cnt, 1);
        g_queue[h] = make_int2(ray, c0 | (c1 << 16));
    }
}

__global__ __launch_bounds__(256) void phaseB_kernel(
    const float* __restrict__ rays_o,
    const float* __restrict__ rays_d,
    const float* __restrict__ sigma_feat,
    const float* __restrict__ rgb,
    const float* __restrict__ aabb,
    float* __restrict__ out,
    int N)
{
    const int lane  = threadIdx.x & 31;
    const int gwarp = (blockIdx.x * blockDim.x + threadIdx.x) >> 5;
    const int nwarp = (gridDim.x * blockDim.x) >> 5;
    const int nh = g_cnt;

    const float ax0 = aabb[0], ay0 = aabb[1], az0 = aabb[2];
    const float ax1 = aabb[3], ay1 = aabb[4], az1 = aabb[5];
    const float NEAR = 2.0f;
    const float DENSITY_SHIFT = -10.0f;
    const float step = 4.0f / 511.0f;
    const float dist = step * 25.0f;

    for (int h = gwarp; h < nh; h += nwarp) {
        const int2 q = g_queue[h];
        const int r  = q.x;
        const int c0 = q.y & 0xffff;
        const int c1 = q.y >> 16;

        const float ox = rays_o[r * 3 + 0];
        const float oy = rays_o[r * 3 + 1];
        const float oz = rays_o[r * 3 + 2];
        const float dx = rays_d[r * 3 + 0];
        const float dy = rays_d[r * 3 + 1];
        const float dz = rays_d[r * 3 + 2];

        const float* __restrict__ sf = sigma_feat + (size_t)r * S_SAMPLES;
        const float* __restrict__ rg = rgb + (size_t)r * S_SAMPLES * 3;

        float runT = 1.0f;
        float racc = 0.0f, gacc = 0.0f, bacc = 0.0f, dacc = 0.0f;

        #pragma unroll 1
        for (int c = c0; c <= c1; ++c) {
            const int s = c * 32 + lane;
            const float t = fmaf(step, (float)s, NEAR);
            const float px = fmaf(dx, t, ox);
            const float py = fmaf(dy, t, oy);
            const float pz = fmaf(dz, t, oz);
            const bool inb = (px >= ax0) & (px <= ax1) &
                             (py >= ay0) & (py <= ay1) &
                             (pz >= az0) & (pz <= az1);

            const float x = sf[s] + DENSITY_SHIFT;
            float sp = (x > 20.0f) ? x : __logf(1.0f + __expf(x));
            const float sigma = inb ? sp : 0.0f;

            const float e = __expf(-sigma * dist);
            const float alpha = 1.0f - e;
            const float f = e + 1e-10f;

            float incl = f;
            #pragma unroll
            for (int off = 1; off < 32; off <<= 1) {
                const float v = __shfl_up_sync(0xffffffffu, incl, off);
                if (lane >= off) incl *= v;
            }
            float excl = __shfl_up_sync(0xffffffffu, incl, 1);
            if (lane == 0) excl = 1.0f;

            const float w = alpha * runT * excl;

            racc += w * rg[s * 3 + 0];
            gacc += w * rg[s * 3 + 1];
            bacc += w * rg[s * 3 + 2];
            dacc += w * t;

            runT *= __shfl_sync(0xffffffffu, incl, 31);
        }

        #pragma unroll
        for (int off = 16; off; off >>= 1) {
            racc += __shfl_down_sync(0xffffffffu, racc, off);
            gacc += __shfl_down_sync(0xffffffffu, gacc, off);
            bacc += __shfl_down_sync(0xffffffffu, bacc, off);
            dacc += __shfl_down_sync(0xffffffffu, dacc, off);
        }

        if (lane == 0) {
            out[r * 3 + 0] = racc;
            out[r * 3 + 1] = gacc;
            out[r * 3 + 2] = bacc;
            out[3 * N + r] = dacc;
            out[4 * N + r] = runT;
        }
    }
}

extern "C" void kernel_launch(void* const* d_in, const int* in_sizes, int n_in,
                              void* d_out, int out_size) {
    const float* rays_o     = (const float*)d_in[0];
    const float* rays_d     = (const float*)d_in[1];
    const float* sigma_feat = (const float*)d_in[2];
    const float* rgb        = (const float*)d_in[3];
    const float* aabb       = (const float*)d_in[4];
    float* out = (float*)d_out;

    const int N = in_sizes[0] / 3;

    reset_kernel<<<1, 1>>>();
    phaseA_kernel<<<(N + 127) / 128, 128>>>(rays_o, rays_d, aabb, out, N);
    phaseB_kernel<<<592, 256>>>(rays_o, rays_d, sigma_feat, rgb, aabb, out, N);
}